// round 3
// baseline (speedup 1.0000x reference)
#include <cuda_runtime.h>
#include <cuda_fp16.h>

#define NF 6
#define H1 64
#define D 32
#define MAXN 100000
#define MAXE 1600000

// ---------------- scratch (static device globals) ----------------------------
__device__ __half g_g1h[MAXN * D];
__device__ __half g_g2h[MAXN * D];
__device__ int    g_cnt[MAXN];
__device__ int    g_rowptr[MAXN + 1];
__device__ int    g_cur[MAXN];
__device__ float  g_dinv[MAXN];
__device__ int    g_csc[MAXE];
__device__ int    g_part[128];
__device__ int    g_is64;
__device__ int    g_bar_cnt;
__device__ volatile int g_bar_gen;

// ---------------- software grid barrier (all blocks resident) ----------------
__device__ __forceinline__ void grid_sync(int nb) {
    __syncthreads();
    if (threadIdx.x == 0) {
        int gen = g_bar_gen;
        __threadfence();
        if (atomicAdd(&g_bar_cnt, 1) == nb - 1) {
            g_bar_cnt = 0;
            __threadfence();
            g_bar_gen = gen + 1;
        } else {
            while (g_bar_gen == gen) __nanosleep(64);
            __threadfence();
        }
    }
    __syncthreads();
}

__device__ __forceinline__ float ldf16cg(const __half* p) {
    unsigned short u = __ldcg((const unsigned short*)p);
    return __half2float(__ushort_as_half(u));
}

__device__ __forceinline__ int e_src(const void* e, int i, int E, bool is64) {
    return is64 ? ((const int*)e)[2 * i] : ((const int*)e)[i];
}
__device__ __forceinline__ int e_dst(const void* e, int i, int E, bool is64) {
    return is64 ? ((const int*)e)[2 * (E + i)] : ((const int*)e)[E + i];
}

// ---------------- the single persistent kernel --------------------------------
__global__ void __launch_bounds__(256, 4) k_mega(
    const float* __restrict__ x, const void* __restrict__ ei,
    const float* __restrict__ We1, const float* __restrict__ be1,
    const float* __restrict__ We2, const float* __restrict__ be2,
    const float* __restrict__ Wg1, const float* __restrict__ bg1,
    const float* __restrict__ Wg2, const float* __restrict__ bg2,
    const float* __restrict__ Wp1, const float* __restrict__ bp1,
    const float* __restrict__ Wp2, const float* __restrict__ bp2,
    float* __restrict__ out, int N, int E, int nb)
{
    __shared__ float sm[3552];   // phase-dependent weight staging
    __shared__ int   swsum[8];

    const int tid  = threadIdx.x;
    const int lane = tid & 31;
    const int wid  = tid >> 5;
    const int gtid = blockIdx.x * 256 + tid;
    const int gstride = nb * 256;
    const int gwarp = blockIdx.x * 8 + wid;
    const int wstride = nb * 8;

    // ---- phase 0: zero counters + dtype detect ----
    for (int i = gtid; i < N; i += gstride) g_cnt[i] = 0;
    if (blockIdx.x == 0 && wid == 0) {
        int v = 0;
        for (int j = lane; j < 2048; j += 32) v |= ((const int*)ei)[2 * j + 1];
#pragma unroll
        for (int off = 16; off; off >>= 1) v |= __shfl_xor_sync(0xffffffffu, v, off);
        if (lane == 0) g_is64 = (v == 0) ? 1 : 0;
    }
    grid_sync(nb);

    const bool is64 = (__ldcg(&g_is64) != 0);

    // ---- phase 1: in-degree histogram ----
    for (int i = gtid; i < E; i += gstride)
        atomicAdd(&g_cnt[e_dst(ei, i, E, is64)], 1);
    grid_sync(nb);

    // ---- phase 2a: per-chunk (1024) exclusive scan ----
    const int nchunk = (N + 1023) >> 10;
    for (int c = blockIdx.x; c < nchunk; c += nb) {
        int i0 = (c << 10) + tid * 4;
        int v0 = (i0 + 0 < N) ? __ldcg(&g_cnt[i0 + 0]) : 0;
        int v1 = (i0 + 1 < N) ? __ldcg(&g_cnt[i0 + 1]) : 0;
        int v2 = (i0 + 2 < N) ? __ldcg(&g_cnt[i0 + 2]) : 0;
        int v3 = (i0 + 3 < N) ? __ldcg(&g_cnt[i0 + 3]) : 0;
        int ts = v0 + v1 + v2 + v3;
        int s = ts;
#pragma unroll
        for (int off = 1; off < 32; off <<= 1) {
            int t = __shfl_up_sync(0xffffffffu, s, off);
            if (lane >= off) s += t;
        }
        if (lane == 31) swsum[wid] = s;
        __syncthreads();
        if (wid == 0 && lane < 8) {
            int w = swsum[lane];
            int ws = w;
#pragma unroll
            for (int off = 1; off < 8; off <<= 1) {
                int t = __shfl_up_sync(0xffu, ws, off, 8);
                if (lane >= off) ws += t;
            }
            swsum[lane] = ws - w;
        }
        __syncthreads();
        int excl = s - ts + swsum[wid];
        if (i0 + 0 < N) g_rowptr[i0 + 0] = excl; excl += v0;
        if (i0 + 1 < N) g_rowptr[i0 + 1] = excl; excl += v1;
        if (i0 + 2 < N) g_rowptr[i0 + 2] = excl; excl += v2;
        if (i0 + 3 < N) g_rowptr[i0 + 3] = excl; excl += v3;
        if (tid == 255) g_part[c] = excl;   // chunk total
        __syncthreads();
    }
    grid_sync(nb);

    // ---- phase 2b: scan the (<=128) chunk totals (block 0, warp 0) ----
    if (blockIdx.x == 0 && wid == 0) {
        int b4 = lane * 4;
        int p0 = (b4 + 0 < nchunk) ? __ldcg(&g_part[b4 + 0]) : 0;
        int p1 = (b4 + 1 < nchunk) ? __ldcg(&g_part[b4 + 1]) : 0;
        int p2 = (b4 + 2 < nchunk) ? __ldcg(&g_part[b4 + 2]) : 0;
        int p3 = (b4 + 3 < nchunk) ? __ldcg(&g_part[b4 + 3]) : 0;
        int ts = p0 + p1 + p2 + p3;
        int s = ts;
#pragma unroll
        for (int off = 1; off < 32; off <<= 1) {
            int t = __shfl_up_sync(0xffffffffu, s, off);
            if (lane >= off) s += t;
        }
        int excl = s - ts;
        if (b4 + 0 < nchunk) g_part[b4 + 0] = excl; excl += p0;
        if (b4 + 1 < nchunk) g_part[b4 + 1] = excl; excl += p1;
        if (b4 + 2 < nchunk) g_part[b4 + 2] = excl; excl += p2;
        if (b4 + 3 < nchunk) g_part[b4 + 3] = excl; excl += p3;
    }
    grid_sync(nb);

    // ---- phase 2c: global rowptr, cursors, dinv ----
    for (int i = gtid; i < N; i += gstride) {
        int r = __ldcg(&g_rowptr[i]) + __ldcg(&g_part[i >> 10]);
        g_rowptr[i] = r;
        g_cur[i] = r;
        g_dinv[i] = rsqrtf((float)(__ldcg(&g_cnt[i]) + 1));
    }
    if (gtid == 0) g_rowptr[N] = E;
    grid_sync(nb);

    // ---- phase 3: CSC fill + embed MLP (independent, run back to back) ----
    for (int i = gtid; i < E; i += gstride) {
        int s = e_src(ei, i, E, is64);
        int d = e_dst(ei, i, E, is64);
        int pos = atomicAdd(&g_cur[d], 1);
        g_csc[pos] = s;
    }
    {
        float* sWe1 = sm;             // 384
        float* sbe1 = sm + 384;       // 64
        float* sWe2 = sm + 448;       // 2048
        float* sbe2 = sm + 2496;      // 32
        float* sWg1 = sm + 2528;      // 1024
        for (int i = tid; i < NF * H1; i += 256) sWe1[i] = We1[i];
        for (int i = tid; i < H1;      i += 256) sbe1[i] = be1[i];
        for (int i = tid; i < H1 * D;  i += 256) sWe2[i] = We2[i];
        for (int i = tid; i < D;       i += 256) sbe2[i] = be2[i];
        for (int i = tid; i < D * D;   i += 256) sWg1[i] = Wg1[i];
        __syncthreads();

        for (int node = gwarp; node < N; node += wstride) {
            float xv = (lane < NF) ? x[node * NF + lane] : 0.f;
            float a = sbe1[lane], b = sbe1[lane + 32];
#pragma unroll
            for (int k = 0; k < NF; k++) {
                float xk = __shfl_sync(0xffffffffu, xv, k);
                a = fmaf(xk, sWe1[k * H1 + lane], a);
                b = fmaf(xk, sWe1[k * H1 + lane + 32], b);
            }
            a = tanhf(a); b = tanhf(b);
            float acc = sbe2[lane];
#pragma unroll
            for (int j = 0; j < 32; j++) {
                float ha = __shfl_sync(0xffffffffu, a, j);
                float hb = __shfl_sync(0xffffffffu, b, j);
                acc = fmaf(ha, sWe2[j * D + lane], acc);
                acc = fmaf(hb, sWe2[(j + 32) * D + lane], acc);
            }
            float h = tanhf(acc);
            float hw = 0.f;
#pragma unroll
            for (int k = 0; k < 32; k++)
                hw = fmaf(__shfl_sync(0xffffffffu, h, k), sWg1[k * D + lane], hw);
            g_g1h[node * D + lane] = __float2half(hw * __ldcg(&g_dinv[node]));
        }
    }
    grid_sync(nb);

    // ---- phase 4: gather conv1 + relu + conv2 linear ----
    {
        float* sW = sm;        // 1024
        float* sb = sm + 1024; // 32
        for (int i = tid; i < D * D; i += 256) sW[i] = Wg2[i];
        for (int i = tid; i < D;     i += 256) sb[i] = bg1[i];
        __syncthreads();

        for (int node = gwarp; node < N; node += wstride) {
            int beg = __ldcg(&g_rowptr[node]), end = __ldcg(&g_rowptr[node + 1]);
            float a0 = ldf16cg(&g_g1h[node * D + lane]);
            float a1 = 0.f, a2 = 0.f, a3 = 0.f;
            int e = beg;
            for (; e + 4 <= end; e += 4) {
                int s0 = __ldcg(&g_csc[e]),     s1 = __ldcg(&g_csc[e + 1]);
                int s2 = __ldcg(&g_csc[e + 2]), s3 = __ldcg(&g_csc[e + 3]);
                a0 += ldf16cg(&g_g1h[s0 * D + lane]);
                a1 += ldf16cg(&g_g1h[s1 * D + lane]);
                a2 += ldf16cg(&g_g1h[s2 * D + lane]);
                a3 += ldf16cg(&g_g1h[s3 * D + lane]);
            }
            for (; e < end; e++) a0 += ldf16cg(&g_g1h[__ldcg(&g_csc[e]) * D + lane]);
            float acc = (a0 + a1) + (a2 + a3);
            float di = __ldcg(&g_dinv[node]);
            float h = fmaxf(fmaf(acc, di, sb[lane]), 0.f);
            float hw = 0.f;
#pragma unroll
            for (int k = 0; k < 32; k++)
                hw = fmaf(__shfl_sync(0xffffffffu, h, k), sW[k * D + lane], hw);
            g_g2h[node * D + lane] = __float2half(hw * di);
        }
    }
    grid_sync(nb);

    // ---- phase 5: gather conv2 + relu + output MLP ----
    {
        float* sW  = sm;         // 1024
        float* sbg = sm + 1024;  // 32
        float* sb1 = sm + 1056;  // 32
        float* sW2 = sm + 1088;  // 32
        float* sb2 = sm + 1120;  // 1
        for (int i = tid; i < D * D; i += 256) sW[i] = Wp1[i];
        for (int i = tid; i < D;     i += 256) { sbg[i] = bg2[i]; sb1[i] = bp1[i]; sW2[i] = Wp2[i]; }
        if (tid == 0) sb2[0] = bp2[0];
        __syncthreads();

        for (int node = gwarp; node < N; node += wstride) {
            int beg = __ldcg(&g_rowptr[node]), end = __ldcg(&g_rowptr[node + 1]);
            float a0 = ldf16cg(&g_g2h[node * D + lane]);
            float a1 = 0.f, a2 = 0.f, a3 = 0.f;
            int e = beg;
            for (; e + 4 <= end; e += 4) {
                int s0 = __ldcg(&g_csc[e]),     s1 = __ldcg(&g_csc[e + 1]);
                int s2 = __ldcg(&g_csc[e + 2]), s3 = __ldcg(&g_csc[e + 3]);
                a0 += ldf16cg(&g_g2h[s0 * D + lane]);
                a1 += ldf16cg(&g_g2h[s1 * D + lane]);
                a2 += ldf16cg(&g_g2h[s2 * D + lane]);
                a3 += ldf16cg(&g_g2h[s3 * D + lane]);
            }
            for (; e < end; e++) a0 += ldf16cg(&g_g2h[__ldcg(&g_csc[e]) * D + lane]);
            float acc = (a0 + a1) + (a2 + a3);
            float di = __ldcg(&g_dinv[node]);
            float h = fmaxf(fmaf(acc, di, sbg[lane]), 0.f);
            float t = sb1[lane];
#pragma unroll
            for (int k = 0; k < 32; k++)
                t = fmaf(__shfl_sync(0xffffffffu, h, k), sW[k * D + lane], t);
            float u = tanhf(t) * sW2[lane];
#pragma unroll
            for (int off = 16; off; off >>= 1)
                u += __shfl_xor_sync(0xffffffffu, u, off);
            if (lane == 0) out[node] = tanhf(u + sb2[0]);
        }
    }
}

// ---------------- launch -------------------------------------------------------
extern "C" void kernel_launch(void* const* d_in, const int* in_sizes, int n_in,
                              void* d_out, int out_size)
{
    const float* x   = (const float*)d_in[0];
    const void*  ei  = d_in[1];
    const float* We1 = (const float*)d_in[2];
    const float* be1 = (const float*)d_in[3];
    const float* We2 = (const float*)d_in[4];
    const float* be2 = (const float*)d_in[5];
    const float* Wg1 = (const float*)d_in[6];
    const float* bg1 = (const float*)d_in[7];
    const float* Wg2 = (const float*)d_in[8];
    const float* bg2 = (const float*)d_in[9];
    const float* Wp1 = (const float*)d_in[10];
    const float* bp1 = (const float*)d_in[11];
    const float* Wp2 = (const float*)d_in[12];
    const float* bp2 = (const float*)d_in[13];

    int N = in_sizes[0] / NF;
    int E = in_sizes[1] / 2;
    if (N > MAXN) N = MAXN;
    if (E > MAXE) E = MAXE;

    int dev = 0, sms = 0, bpm = 0;
    cudaGetDevice(&dev);
    cudaDeviceGetAttribute(&sms, cudaDevAttrMultiProcessorCount, dev);
    cudaOccupancyMaxActiveBlocksPerMultiprocessor(&bpm, k_mega, 256, 0);
    if (bpm < 1) bpm = 1;
    int nb = sms * bpm;
    if (nb > 4096) nb = 4096;

    k_mega<<<nb, 256>>>(x, ei, We1, be1, We2, be2, Wg1, bg1, Wg2, bg2,
                        Wp1, bp1, Wp2, bp2, (float*)d_out, N, E, nb);
}